// round 5
// baseline (speedup 1.0000x reference)
#include <cuda_runtime.h>
#include <cuda_bf16.h>
#include <cstdint>
#include <cstddef>

#define S_LEN 2048
#define B_SZ  128
#define H_SZ  128
#define I_SZ  64
#define O_SZ  64
#define GC    512

// Scratch (device globals per allocation rules)
__device__ float g_pre[(size_t)S_LEN * B_SZ * GC];   // [t][b][gcol]  512 MB
__device__ float g_hs [(size_t)B_SZ * S_LEN * H_SZ]; // [b][t][h]     128 MB

typedef unsigned long long ull;

__device__ __forceinline__ ull pk2(float lo, float hi) {
    ull r;
    asm("mov.b64 %0, {%1, %2};" : "=l"(r)
        : "r"(__float_as_uint(lo)), "r"(__float_as_uint(hi)));
    return r;
}
__device__ __forceinline__ void upk2(ull v, float& lo, float& hi) {
    unsigned int a, b;
    asm("mov.b64 {%0, %1}, %2;" : "=r"(a), "=r"(b) : "l"(v));
    lo = __uint_as_float(a); hi = __uint_as_float(b);
}
#define FMA2(acc, va, vb) asm("fma.rn.f32x2 %0, %1, %2, %0;" : "+l"(acc) : "l"(va), "l"(vb))

__device__ __forceinline__ float sigm(float v)  { return __fdividef(1.0f, 1.0f + __expf(-v)); }
__device__ __forceinline__ float tanhx(float v) { return 1.0f - __fdividef(2.0f, __expf(2.0f * v) + 1.0f); }

__device__ __forceinline__ void csync() {
    asm volatile("barrier.cluster.arrive.aligned;" ::: "memory");
    asm volatile("barrier.cluster.wait.aligned;"   ::: "memory");
}
__device__ __forceinline__ void stc(uint32_t local_addr, uint32_t rk, float v) {
    uint32_t ra;
    asm("mapa.shared::cluster.u32 %0, %1, %2;" : "=r"(ra) : "r"(local_addr), "r"(rk));
    asm volatile("st.shared::cluster.f32 [%0], %1;" :: "r"(ra), "f"(v) : "memory");
}

// ---------------------------------------------------------------------------
// Phase 1: g_pre[t][b][gcol] = sum_i x[b][i][t] * Wx_out[i][gcol]
// ---------------------------------------------------------------------------
__global__ void __launch_bounds__(256) pre_kernel(const float* __restrict__ x,
                                                  const float* __restrict__ Wx)
{
    __shared__ __align__(16) float sX[64][65];  // [t][i]
    __shared__ __align__(16) float sW[64][68];  // [i][c]
    const int t0  = blockIdx.x * 64;
    const int c0  = blockIdx.y * 64;
    const int b   = blockIdx.z;
    const int tid = threadIdx.x;

    for (int idx = tid; idx < 4096; idx += 256) {
        int hi = idx >> 6, lo = idx & 63;
        sX[lo][hi] = x[(size_t)b * (I_SZ * S_LEN) + (size_t)hi * S_LEN + t0 + lo];
        sW[hi][lo] = Wx[hi * GC + c0 + lo];
    }
    __syncthreads();

    const int ty = tid >> 4, tx = tid & 15;
    const int r0 = ty * 4, c4 = tx * 4;
    float acc[4][4] = {};
#pragma unroll 8
    for (int k = 0; k < 64; ++k) {
        float4 bv = *(const float4*)&sW[k][c4];
#pragma unroll
        for (int u = 0; u < 4; ++u) {
            float a = sX[r0 + u][k];
            acc[u][0] += a * bv.x; acc[u][1] += a * bv.y;
            acc[u][2] += a * bv.z; acc[u][3] += a * bv.w;
        }
    }
#pragma unroll
    for (int u = 0; u < 4; ++u) {
        float4 v = make_float4(acc[u][0], acc[u][1], acc[u][2], acc[u][3]);
        *(float4*)&g_pre[((size_t)(t0 + r0 + u) * B_SZ + b) * GC + c0 + c4] = v;
    }
}

// ---------------------------------------------------------------------------
// Phase 2: recurrence. 32 clusters x 4 CTAs. Cluster owns 4 batch rows.
// CTA rank r owns gate columns gcol = g*128 + r*32 + jj  (g=0..3, jj=0..31),
// i.e. all four gates of H-slice [r*32, r*32+32). Weights in smem [k][c].
// Activations broadcast cluster-wide via DSMEM, 2 cluster syncs / step.
// ---------------------------------------------------------------------------
#define REC_SMEM_FLOATS (3 * 16384 + 3 * 512 + 640)
#define REC_SMEM_BYTES  (REC_SMEM_FLOATS * 4)

__global__ void __cluster_dims__(4, 1, 1) __launch_bounds__(128, 1)
rec_kernel(const float* __restrict__ Wh_out, const float* __restrict__ Wx_in,
           const float* __restrict__ Wh_in,  const float* __restrict__ b_out,
           const float* __restrict__ b_in)
{
    extern __shared__ __align__(16) float sm[];
    float* sWh  = sm;                 // [k][128]
    float* sWxi = sWh  + 16384;
    float* sWhi = sWxi + 16384;
    float* sH   = sWhi + 16384;       // [k][4]  (4 batch rows per k)
    float* sXin = sH   + 512;
    float* sHin = sXin + 512;
    float* sG   = sHin + 512;         // [c][5]  gate scratch (pad 5: conflict-free)

    const int tid = threadIdx.x;
    unsigned int rank;
    asm("mov.u32 %0, %%cluster_ctarank;" : "=r"(rank));
    const int bb = blockIdx.x & ~3;   // batch base of this cluster

    const int gcolc = ((tid >> 5) << 7) + (int)rank * 32 + (tid & 31);
    for (int k = 0; k < 128; ++k) {
        sWh [k * 128 + tid] = Wh_out[k * GC + gcolc];
        sWxi[k * 128 + tid] = Wx_in [k * GC + gcolc];
        sWhi[k * 128 + tid] = Wh_in [k * GC + gcolc];
    }
    sH[tid] = 0.0f; sH[tid + 128] = 0.0f; sH[tid + 256] = 0.0f; sH[tid + 384] = 0.0f;
    const float bo = b_out[gcolc];
    const float bi = b_in[gcolc];

    // Epilogue role: thread (b2, jj) owns state for batch bb+b2, H-col J
    const int b2 = tid >> 5, jj = tid & 31;
    const int J  = (int)rank * 32 + jj;
    const uint32_t aH   = (uint32_t)__cvta_generic_to_shared(&sH  [J * 4 + b2]);
    const uint32_t aXin = (uint32_t)__cvta_generic_to_shared(&sXin[J * 4 + b2]);
    const uint32_t aHin = (uint32_t)__cvta_generic_to_shared(&sHin[J * 4 + b2]);

    float c_st = 0.0f, cn_st = 0.0f;

    csync();  // weights + h0 ready cluster-wide

    const float* preb = g_pre + (size_t)bb * GC + gcolc;

    for (int t = 0; t < S_LEN; ++t) {
        // prefetch pre-activations (consumed in epilogue1 — long slack)
        const float* pp = preb + (size_t)t * (B_SZ * GC);
        float p0 = pp[0], p1 = pp[GC], p2 = pp[2 * GC], p3 = pp[3 * GC];

        // ---- outer GEMM: acc[b] = sum_k h[b][k] * Wh_out[k][c] ----
        ull acc01 = 0, acc23 = 0;
        {
            const float* wp = sWh + tid;
#pragma unroll 8
            for (int k = 0; k < 128; ++k) {
                ulonglong2 h2 = *(const ulonglong2*)(sH + k * 4);  // broadcast
                float w = wp[k * 128];
                ull ww = pk2(w, w);
                FMA2(acc01, h2.x, ww);
                FMA2(acc23, h2.y, ww);
            }
        }
        float a0, a1, a2, a3;
        upk2(acc01, a0, a1); upk2(acc23, a2, a3);
        sG[tid * 5 + 0] = a0 + p0 + bo;
        sG[tid * 5 + 1] = a1 + p1 + bo;
        sG[tid * 5 + 2] = a2 + p2 + bo;
        sG[tid * 5 + 3] = a3 + p3 + bo;
        __syncthreads();

        // ---- epilogue 1: gates -> x_in, h_in; broadcast cluster-wide ----
        float gi = sG[(jj     ) * 5 + b2];
        float gf = sG[(32 + jj) * 5 + b2];
        float go = sG[(64 + jj) * 5 + b2];
        float gg = sG[(96 + jj) * 5 + b2];
        float o_g  = sigm(go);
        float x_in = sigm(gi) * tanhx(gg);
        float h_in = sigm(gf) * c_st;
#pragma unroll
        for (int rk = 0; rk < 4; ++rk) { stc(aXin, rk, x_in); stc(aHin, rk, h_in); }
        csync();

        // ---- inner GEMMs: gi[b][c] = x_in@Wx_in + h_in@Wh_in ----
        acc01 = 0; acc23 = 0;
        {
            const float* wpx = sWxi + tid;
            const float* wph = sWhi + tid;
#pragma unroll 4
            for (int k = 0; k < 128; ++k) {
                ulonglong2 x2 = *(const ulonglong2*)(sXin + k * 4);
                ulonglong2 hh = *(const ulonglong2*)(sHin + k * 4);
                float wx = wpx[k * 128];
                float wh = wph[k * 128];
                ull wwx = pk2(wx, wx), wwh = pk2(wh, wh);
                FMA2(acc01, x2.x, wwx);
                FMA2(acc23, x2.y, wwx);
                FMA2(acc01, hh.x, wwh);
                FMA2(acc23, hh.y, wwh);
            }
        }
        upk2(acc01, a0, a1); upk2(acc23, a2, a3);
        sG[tid * 5 + 0] = a0 + bi;
        sG[tid * 5 + 1] = a1 + bi;
        sG[tid * 5 + 2] = a2 + bi;
        sG[tid * 5 + 3] = a3 + bi;
        __syncthreads();

        // ---- epilogue 2: inner LSTM update, h_new broadcast + store ----
        float ii = sG[(jj     ) * 5 + b2];
        float fi = sG[(32 + jj) * 5 + b2];
        float oi = sG[(64 + jj) * 5 + b2];
        float g2 = sG[(96 + jj) * 5 + b2];
        cn_st = sigm(fi) * cn_st + sigm(ii) * tanhx(g2);
        c_st  = sigm(oi) * tanhx(cn_st);
        float h_new = o_g * tanhx(c_st);
        g_hs[((size_t)(bb + b2) * S_LEN + t) * H_SZ + J] = h_new;
#pragma unroll
        for (int rk = 0; rk < 4; ++rk) stc(aH, rk, h_new);
        csync();
    }
}

// ---------------------------------------------------------------------------
// Phase 3: out[m][n] = g_hs[m][:] @ W_lin[n][:] + b_lin[n],  m = b*S + s
// ---------------------------------------------------------------------------
__global__ void __launch_bounds__(256) lin_kernel(const float* __restrict__ W_lin,
                                                  const float* __restrict__ b_lin,
                                                  float* __restrict__ out)
{
    __shared__ __align__(16) float sA[64][68];  // [row][k]
    __shared__ __align__(16) float sB[64][68];  // [k][n]
    const int m0  = blockIdx.x * 64;
    const int tid = threadIdx.x;
    const int ty = tid >> 4, tx = tid & 15;
    const int r0 = ty * 4, c4 = tx * 4;

    float acc[4][4] = {};
    for (int kb = 0; kb < H_SZ; kb += 64) {
        for (int idx = tid; idx < 4096; idx += 256) {
            int hi = idx >> 6, lo = idx & 63;
            sA[hi][lo] = g_hs[(size_t)(m0 + hi) * H_SZ + kb + lo];
            sB[lo][hi] = W_lin[hi * H_SZ + kb + lo];
        }
        __syncthreads();
#pragma unroll 8
        for (int k = 0; k < 64; ++k) {
            float4 bv = *(const float4*)&sB[k][c4];
#pragma unroll
            for (int u = 0; u < 4; ++u) {
                float a = sA[r0 + u][k];
                acc[u][0] += a * bv.x; acc[u][1] += a * bv.y;
                acc[u][2] += a * bv.z; acc[u][3] += a * bv.w;
            }
        }
        __syncthreads();
    }
    float4 bl = *(const float4*)&b_lin[c4];
#pragma unroll
    for (int u = 0; u < 4; ++u) {
        float4 v = make_float4(acc[u][0] + bl.x, acc[u][1] + bl.y,
                               acc[u][2] + bl.z, acc[u][3] + bl.w);
        *(float4*)&out[(size_t)(m0 + r0 + u) * O_SZ + c4] = v;
    }
}

// ---------------------------------------------------------------------------
extern "C" void kernel_launch(void* const* d_in, const int* in_sizes, int n_in,
                              void* d_out, int out_size)
{
    (void)in_sizes; (void)n_in; (void)out_size;
    const float* x      = (const float*)d_in[0];
    const float* Wx_out = (const float*)d_in[1];
    const float* Wh_out = (const float*)d_in[2];
    const float* b_out  = (const float*)d_in[3];
    const float* Wx_in  = (const float*)d_in[4];
    const float* Wh_in  = (const float*)d_in[5];
    const float* b_in   = (const float*)d_in[6];
    const float* W_lin  = (const float*)d_in[7];
    const float* b_lin  = (const float*)d_in[8];
    float* out = (float*)d_out;

    pre_kernel<<<dim3(S_LEN / 64, GC / 64, B_SZ), 256>>>(x, Wx_out);

    cudaFuncSetAttribute(rec_kernel, cudaFuncAttributeMaxDynamicSharedMemorySize,
                         REC_SMEM_BYTES);
    rec_kernel<<<128, 128, REC_SMEM_BYTES>>>(Wh_out, Wx_in, Wh_in, b_out, b_in);

    lin_kernel<<<(B_SZ * S_LEN) / 64, 256>>>(W_lin, b_lin, out);
}